// round 1
// baseline (speedup 1.0000x reference)
#include <cuda_runtime.h>
#include <cuda_bf16.h>
#include <math.h>

// Problem shape (fixed by the dataset)
#define BB 4
#define SS 2048
#define DD 1024
#define MM (BB*SS)   // 8192

// ---------------- scratch (no allocations allowed) ----------------
__device__ float g_Q[MM*DD];
__device__ float g_K[MM*DD];
__device__ float g_V[MM*DD];
__device__ float g_S[(long long)BB*SS*SS];  // scores / probs (in-place softmax)
__device__ float g_A[MM*DD];

// ---------------- SGEMM: C = alpha * A @ B^T  (TN: both K-major) ----------------
// A: M x K row-major, B: N x K row-major, C: M x N row-major.
// 128x128 tile, BK=8, 256 threads, 8x8 microtile.
#define BM 128
#define BN 128
#define BK 8

__global__ void __launch_bounds__(256) sgemm_tn(
    const float* __restrict__ A, const float* __restrict__ B, float* __restrict__ C,
    int M, int N, int K,
    long long sA, long long sB, long long sC,
    float alpha, int causalSkip)
{
    int bz = blockIdx.z;
    const float* Ab = A + (long long)bz * sA;
    const float* Bb = B + (long long)bz * sB;
    float*       Cb = C + (long long)bz * sC;

    int m0 = blockIdx.y * BM;
    int n0 = blockIdx.x * BN;
    // scores: tile entirely above the causal diagonal -> never read, skip
    if (causalSkip && n0 >= m0 + BM) return;

    __shared__ float As[BK][BM];
    __shared__ float Bs[BK][BN];

    int tid = threadIdx.x;
    int tx = tid & 15;          // 0..15
    int ty = tid >> 4;          // 0..15
    int lr = tid >> 1;          // 0..127  (row within tile for loads)
    int lk = (tid & 1) * 4;     // 0 or 4  (k offset for float4 load)

    const float* Aptr = Ab + (long long)(m0 + lr) * K + lk;
    const float* Bptr = Bb + (long long)(n0 + lr) * K + lk;

    float acc[8][8];
    #pragma unroll
    for (int i = 0; i < 8; i++)
        #pragma unroll
        for (int j = 0; j < 8; j++) acc[i][j] = 0.f;

    for (int k0 = 0; k0 < K; k0 += BK) {
        float4 av = *(const float4*)(Aptr + k0);
        float4 bv = *(const float4*)(Bptr + k0);
        As[lk+0][lr] = av.x; As[lk+1][lr] = av.y; As[lk+2][lr] = av.z; As[lk+3][lr] = av.w;
        Bs[lk+0][lr] = bv.x; Bs[lk+1][lr] = bv.y; Bs[lk+2][lr] = bv.z; Bs[lk+3][lr] = bv.w;
        __syncthreads();

        #pragma unroll
        for (int kk = 0; kk < BK; kk++) {
            float4 a0 = *(const float4*)&As[kk][ty*4];
            float4 a1 = *(const float4*)&As[kk][ty*4 + 64];
            float4 b0 = *(const float4*)&Bs[kk][tx*4];
            float4 b1 = *(const float4*)&Bs[kk][tx*4 + 64];
            float a[8] = {a0.x,a0.y,a0.z,a0.w, a1.x,a1.y,a1.z,a1.w};
            float b[8] = {b0.x,b0.y,b0.z,b0.w, b1.x,b1.y,b1.z,b1.w};
            #pragma unroll
            for (int i = 0; i < 8; i++)
                #pragma unroll
                for (int j = 0; j < 8; j++)
                    acc[i][j] += a[i] * b[j];
        }
        __syncthreads();
    }

    #pragma unroll
    for (int ih = 0; ih < 2; ih++) {
        #pragma unroll
        for (int ii = 0; ii < 4; ii++) {
            int m = m0 + ih*64 + ty*4 + ii;
            #pragma unroll
            for (int jh = 0; jh < 2; jh++) {
                int i = ih*4 + ii;
                float4 v = make_float4(acc[i][jh*4+0]*alpha, acc[i][jh*4+1]*alpha,
                                       acc[i][jh*4+2]*alpha, acc[i][jh*4+3]*alpha);
                *(float4*)&Cb[(long long)m * N + n0 + jh*64 + tx*4] = v;
            }
        }
    }
}

// ---------------- SGEMM: C = alpha * A @ B  (NN) ----------------
// A: M x K row-major, B: K x N row-major. Optional causal K-truncation:
// block row [m0, m0+BM) only needs k < m0+BM (P is zero beyond the diagonal).
__global__ void __launch_bounds__(256) sgemm_nn(
    const float* __restrict__ A, const float* __restrict__ B, float* __restrict__ C,
    int M, int N, int K,
    long long sA, long long sB, long long sC,
    float alpha, int causalK)
{
    int bz = blockIdx.z;
    const float* Ab = A + (long long)bz * sA;
    const float* Bb = B + (long long)bz * sB;
    float*       Cb = C + (long long)bz * sC;

    int m0 = blockIdx.y * BM;
    int n0 = blockIdx.x * BN;
    int Keff = causalK ? min(K, m0 + BM) : K;

    __shared__ float As[BK][BM];
    __shared__ float Bs[BK][BN];

    int tid = threadIdx.x;
    int tx = tid & 15;
    int ty = tid >> 4;
    int lr  = tid >> 1;          // A: row 0..127
    int lk  = (tid & 1) * 4;     // A: k offset
    int lkB = tid >> 5;          // B: k row 0..7
    int lnB = (tid & 31) * 4;    // B: n offset 0..124

    const float* Aptr = Ab + (long long)(m0 + lr) * K + lk;
    const float* Bptr = Bb + (long long)lkB * N + n0 + lnB;

    float acc[8][8];
    #pragma unroll
    for (int i = 0; i < 8; i++)
        #pragma unroll
        for (int j = 0; j < 8; j++) acc[i][j] = 0.f;

    for (int k0 = 0; k0 < Keff; k0 += BK) {
        float4 av = *(const float4*)(Aptr + k0);
        float4 bv = *(const float4*)(Bptr + (long long)k0 * N);
        As[lk+0][lr] = av.x; As[lk+1][lr] = av.y; As[lk+2][lr] = av.z; As[lk+3][lr] = av.w;
        *(float4*)&Bs[lkB][lnB] = bv;
        __syncthreads();

        #pragma unroll
        for (int kk = 0; kk < BK; kk++) {
            float4 a0 = *(const float4*)&As[kk][ty*4];
            float4 a1 = *(const float4*)&As[kk][ty*4 + 64];
            float4 b0 = *(const float4*)&Bs[kk][tx*4];
            float4 b1 = *(const float4*)&Bs[kk][tx*4 + 64];
            float a[8] = {a0.x,a0.y,a0.z,a0.w, a1.x,a1.y,a1.z,a1.w};
            float b[8] = {b0.x,b0.y,b0.z,b0.w, b1.x,b1.y,b1.z,b1.w};
            #pragma unroll
            for (int i = 0; i < 8; i++)
                #pragma unroll
                for (int j = 0; j < 8; j++)
                    acc[i][j] += a[i] * b[j];
        }
        __syncthreads();
    }

    #pragma unroll
    for (int ih = 0; ih < 2; ih++) {
        #pragma unroll
        for (int ii = 0; ii < 4; ii++) {
            int m = m0 + ih*64 + ty*4 + ii;
            #pragma unroll
            for (int jh = 0; jh < 2; jh++) {
                int i = ih*4 + ii;
                float4 v = make_float4(acc[i][jh*4+0]*alpha, acc[i][jh*4+1]*alpha,
                                       acc[i][jh*4+2]*alpha, acc[i][jh*4+3]*alpha);
                *(float4*)&Cb[(long long)m * N + n0 + jh*64 + tx*4] = v;
            }
        }
    }
}

// ---------------- RoPE (in-place on Q and K) ----------------
// token_positions may be int32 or int64 depending on JAX x64 config; detect:
// data is tile(arange(S)) so element 1 == 1. As int32 words, int64-LE gives
// word[1] == 0 (high word of element 0), int32 gives word[1] == 1.
__global__ void rope_kernel(float* __restrict__ Q, float* __restrict__ Kt,
                            const int* __restrict__ pos32)
{
    long long idx = (long long)blockIdx.x * blockDim.x + threadIdx.x;
    const int half = DD / 2;
    long long total = (long long)BB * SS * half;
    if (idx >= total) return;

    int i = (int)(idx % half);
    long long row = idx / half;            // b*S + s
    bool is64 = (pos32[1] == 0);
    int p = is64 ? pos32[2*row] : pos32[row];

    double ang = (double)p * exp(-log(10000.0) * (2.0 * (double)i / (double)DD));
    float c, sn;
    sincosf((float)ang, &sn, &c);

    long long off = row * DD + 2*i;
    float q1 = Q[off], q2 = Q[off+1];
    Q[off]   = q1*c - q2*sn;
    Q[off+1] = q1*sn + q2*c;
    float k1 = Kt[off], k2 = Kt[off+1];
    Kt[off]   = k1*c - k2*sn;
    Kt[off+1] = k1*sn + k2*c;
}

// ---------------- causal softmax, in place, one block per row ----------------
__device__ __forceinline__ float warpMax(float v) {
    #pragma unroll
    for (int o = 16; o; o >>= 1) v = fmaxf(v, __shfl_xor_sync(0xffffffffu, v, o));
    return v;
}
__device__ __forceinline__ float warpSum(float v) {
    #pragma unroll
    for (int o = 16; o; o >>= 1) v += __shfl_xor_sync(0xffffffffu, v, o);
    return v;
}

__global__ void __launch_bounds__(256) softmax_causal(float* __restrict__ Sc)
{
    int q = blockIdx.x;
    int b = blockIdx.y;
    float* row = Sc + ((long long)b * SS + q) * SS;
    int L = q + 1;
    int tid = threadIdx.x;
    int warp = tid >> 5, lane = tid & 31;
    __shared__ float red[8];

    float m = -1e30f;
    for (int j = tid; j < L; j += 256) m = fmaxf(m, row[j]);
    m = warpMax(m);
    if (lane == 0) red[warp] = m;
    __syncthreads();
    m = (lane < 8) ? red[lane] : -1e30f;
    m = warpMax(m);
    m = __shfl_sync(0xffffffffu, m, 0);

    float sum = 0.f;
    for (int j = tid; j < L; j += 256) {
        float e = __expf(row[j] - m);
        row[j] = e;
        sum += e;
    }
    sum = warpSum(sum);
    __syncthreads();
    if (lane == 0) red[warp] = sum;
    __syncthreads();
    sum = (lane < 8) ? red[lane] : 0.f;
    sum = warpSum(sum);
    sum = __shfl_sync(0xffffffffu, sum, 0);
    float inv = 1.f / sum;

    for (int j = tid; j < L; j += 256) row[j] *= inv;
    for (int j = L + tid; j < SS; j += 256) row[j] = 0.f;   // PV reads full rows
}

// ---------------- launch ----------------
extern "C" void kernel_launch(void* const* d_in, const int* in_sizes, int n_in,
                              void* d_out, int out_size)
{
    const float* x  = (const float*)d_in[0];
    const float* Wq = (const float*)d_in[1];
    const float* Wk = (const float*)d_in[2];
    const float* Wv = (const float*)d_in[3];
    const float* Wo = (const float*)d_in[4];
    const int*   pos = (const int*)d_in[5];
    float* out = (float*)d_out;

    static float *pQ = nullptr, *pK = nullptr, *pV = nullptr, *pS = nullptr, *pA = nullptr;
    if (!pQ) {
        cudaGetSymbolAddress((void**)&pQ, g_Q);
        cudaGetSymbolAddress((void**)&pK, g_K);
        cudaGetSymbolAddress((void**)&pV, g_V);
        cudaGetSymbolAddress((void**)&pS, g_S);
        cudaGetSymbolAddress((void**)&pA, g_A);
    }

    dim3 blk(256);
    dim3 gProj(DD / BN, MM / BM, 1);                 // (8, 64)

    // Q/K/V projections: y = x @ W^T
    sgemm_tn<<<gProj, blk>>>(x, Wq, pQ, MM, DD, DD, 0, 0, 0, 1.f, 0);
    sgemm_tn<<<gProj, blk>>>(x, Wk, pK, MM, DD, DD, 0, 0, 0, 1.f, 0);
    sgemm_tn<<<gProj, blk>>>(x, Wv, pV, MM, DD, DD, 0, 0, 0, 1.f, 0);

    // RoPE on Q and K
    long long ropeThreads = (long long)BB * SS * (DD / 2);
    rope_kernel<<<(unsigned)((ropeThreads + 255) / 256), 256>>>(pQ, pK, pos);

    // scores = Q @ K^T / sqrt(D), per batch, upper-triangle tiles skipped
    dim3 gS(SS / BN, SS / BM, BB);                   // (16, 16, 4)
    sgemm_tn<<<gS, blk>>>(pQ, pK, pS, SS, SS, DD,
                          (long long)SS * DD, (long long)SS * DD, (long long)SS * SS,
                          0.03125f, 1);

    // causal softmax in place (zero-fills masked tail)
    softmax_causal<<<dim3(SS, BB), 256>>>(pS);

    // attn = P @ V, per batch, K-loop truncated at diagonal
    dim3 gPV(DD / BN, SS / BM, BB);                  // (8, 16, 4)
    sgemm_nn<<<gPV, blk>>>(pS, pV, pA, SS, DD, SS,
                           (long long)SS * SS, (long long)SS * DD, (long long)SS * DD,
                           1.f, 1);

    // out = attn @ Wo^T
    sgemm_tn<<<gProj, blk>>>(pA, Wo, out, MM, DD, DD, 0, 0, 0, 1.f, 0);
}

// round 3
// speedup vs baseline: 3.1759x; 3.1759x over previous
#include <cuda_runtime.h>
#include <math.h>
#include <stdint.h>

// Problem shape (fixed)
#define BB 4
#define SS 2048
#define DD 1024
#define MM (BB*SS)   // 8192

// ---------------- scratch ----------------
__device__ float g_Q[MM*DD];
__device__ float g_K[MM*DD];
__device__ float g_Vt[MM*DD];                 // V projected, transposed per batch: [b][d][s]
__device__ float g_S[(long long)BB*SS*SS];    // scores / probs
__device__ float g_A[MM*DD];

// ---------------- helpers ----------------
__device__ __forceinline__ uint32_t smem_u32(const void* p) {
    uint32_t a;
    asm("{ .reg .u64 t; cvta.to.shared.u64 t, %1; cvt.u32.u64 %0, t; }" : "=r"(a) : "l"(p));
    return a;
}
__device__ __forceinline__ void cp16(uint32_t dst, const void* src) {
    asm volatile("cp.async.cg.shared.global [%0], [%1], 16;" :: "r"(dst), "l"(src));
}
#define CP_COMMIT() asm volatile("cp.async.commit_group;" ::: "memory")
#define CP_WAIT1()  asm volatile("cp.async.wait_group 1;"  ::: "memory")

// chunk-swizzled smem offset: row stride 64B (16 floats), 16B chunk rotated by row>>1
#define SWOFF(row, c) ((uint32_t)((row)*64 + (((((c) + ((row)>>1))) & 3) << 4)))

__device__ __forceinline__ uint32_t frag_ld(const char* p, int row, int c, int w) {
    const float* q = (const float*)(p + SWOFF(row, c));
    float f = q[w];
    uint32_t u;
    asm("cvt.rna.tf32.f32 %0, %1;" : "=r"(u) : "f"(f));
    return u;
}

#define MMA_TF32(cc, aa, bb) \
    asm volatile("mma.sync.aligned.m16n8k8.row.col.f32.tf32.tf32.f32 " \
        "{%0,%1,%2,%3}, {%4,%5,%6,%7}, {%8,%9}, {%0,%1,%2,%3};" \
        : "+f"((cc)[0]), "+f"((cc)[1]), "+f"((cc)[2]), "+f"((cc)[3]) \
        : "r"((aa)[0]), "r"((aa)[1]), "r"((aa)[2]), "r"((aa)[3]), \
          "r"((bb)[0]), "r"((bb)[1]))

// ================= tf32 mma.sync GEMM: C = alpha * A @ B^T (TN) =================
// A: M x K row-major, B: N x K row-major, both lda=ldb=K. C: M x N row-major.
// 128x128 tile, BK=16, 3-stage cp.async, 8 warps (2x4), warp tile 64x32.
// mode: 0 plain | 1 causal tile-skip | 2 causal K-trunc | 3 transposed-per-batch output
#define STAGE 16384           // A 8KB + B 8KB
#define SM_TOTAL (3*STAGE)    // 49152

__global__ void __launch_bounds__(256, 2) gemm_mma(
    const float* __restrict__ A, const float* __restrict__ B, float* __restrict__ C,
    int M, int N, int K,
    long long sA, long long sB, long long sC,
    float alpha, int mode)
{
    extern __shared__ char smem[];
    int bz = blockIdx.z;
    const float* Ab = A + (long long)bz * sA;
    const float* Bb = B + (long long)bz * sB;

    int m0 = blockIdx.y * 128;
    int n0 = blockIdx.x * 128;
    if (mode == 1 && n0 >= m0 + 128) return;
    int Keff  = (mode == 2) ? min(K, m0 + 128) : K;
    int nIter = Keff >> 4;

    int tid = threadIdx.x, wid = tid >> 5, lane = tid & 31;
    int warp_m = wid >> 2, warp_n = wid & 3;
    int g = lane >> 2, w = lane & 3;
    uint32_t sb = smem_u32(smem);

    // global->smem load mapping: thread -> row tid>>1, chunks (tid&1)*2, +1
    int rowL = tid >> 1, cL = (tid & 1) * 2;
    uint32_t dOff0 = SWOFF(rowL, cL);
    uint32_t dOff1 = SWOFF(rowL, cL + 1);
    const float* gAp = Ab + (long long)(m0 + rowL) * K + cL * 4;
    const float* gBp = Bb + (long long)(n0 + rowL) * K + cL * 4;

    float acc[4][4][4];
    #pragma unroll
    for (int i = 0; i < 4; i++)
        #pragma unroll
        for (int j = 0; j < 4; j++)
            #pragma unroll
            for (int q = 0; q < 4; q++) acc[i][j][q] = 0.f;

    // prologue: stages 0,1
    #pragma unroll
    for (int s = 0; s < 2; s++) {
        uint32_t base = sb + s * STAGE;
        int k0 = s * 16;
        cp16(base + dOff0,        gAp + k0);
        cp16(base + dOff1,        gAp + k0 + 4);
        cp16(base + 8192 + dOff0, gBp + k0);
        cp16(base + 8192 + dOff1, gBp + k0 + 4);
        CP_COMMIT();
    }

    for (int kt = 0; kt < nIter; kt++) {
        CP_WAIT1();
        __syncthreads();

        const char* pA = smem + (kt % 3) * STAGE;
        const char* pB = pA + 8192;
        #pragma unroll
        for (int ks = 0; ks < 2; ks++) {
            uint32_t af[4][4], bf[4][2];
            #pragma unroll
            for (int mf = 0; mf < 4; mf++) {
                int r = warp_m * 64 + mf * 16 + g;
                af[mf][0] = frag_ld(pA, r,     ks*2,     w);
                af[mf][1] = frag_ld(pA, r + 8, ks*2,     w);
                af[mf][2] = frag_ld(pA, r,     ks*2 + 1, w);
                af[mf][3] = frag_ld(pA, r + 8, ks*2 + 1, w);
            }
            #pragma unroll
            for (int nf = 0; nf < 4; nf++) {
                int nr = warp_n * 32 + nf * 8 + g;
                bf[nf][0] = frag_ld(pB, nr, ks*2,     w);
                bf[nf][1] = frag_ld(pB, nr, ks*2 + 1, w);
            }
            #pragma unroll
            for (int mf = 0; mf < 4; mf++)
                #pragma unroll
                for (int nf = 0; nf < 4; nf++)
                    MMA_TF32(acc[mf][nf], af[mf], bf[nf]);
        }

        int nk = kt + 2;
        if (nk < nIter) {
            uint32_t base = sb + (nk % 3) * STAGE;
            int k0 = nk * 16;
            cp16(base + dOff0,        gAp + k0);
            cp16(base + dOff1,        gAp + k0 + 4);
            cp16(base + 8192 + dOff0, gBp + k0);
            cp16(base + 8192 + dOff1, gBp + k0 + 4);
        }
        CP_COMMIT();
    }

    if (mode != 3) {
        float* Cb = C + (long long)bz * sC;
        #pragma unroll
        for (int mf = 0; mf < 4; mf++) {
            int r0 = m0 + warp_m * 64 + mf * 16 + g;
            #pragma unroll
            for (int nf = 0; nf < 4; nf++) {
                int col = n0 + warp_n * 32 + nf * 8 + w * 2;
                float2 v0 = make_float2(acc[mf][nf][0] * alpha, acc[mf][nf][1] * alpha);
                float2 v1 = make_float2(acc[mf][nf][2] * alpha, acc[mf][nf][3] * alpha);
                *(float2*)&Cb[(long long)r0 * N + col]       = v0;
                *(float2*)&Cb[(long long)(r0 + 8) * N + col] = v1;
            }
        }
    } else {
        // transposed epilogue: stage 128x32 column block through smem, store d-major
        float* Ts = (float*)smem;                 // [128][33]
        int b = m0 / SS;
        int srow0 = m0 % SS;
        float* Cb = C + (long long)b * sC;        // sC = DD*SS
        #pragma unroll
        for (int nc = 0; nc < 4; nc++) {
            __syncthreads();
            if (warp_n == nc) {
                #pragma unroll
                for (int mf = 0; mf < 4; mf++) {
                    int mloc = warp_m * 64 + mf * 16 + g;
                    #pragma unroll
                    for (int nf = 0; nf < 4; nf++) {
                        int d = nf * 8 + w * 2;
                        Ts[mloc * 33 + d]           = acc[mf][nf][0];
                        Ts[mloc * 33 + d + 1]       = acc[mf][nf][1];
                        Ts[(mloc + 8) * 33 + d]     = acc[mf][nf][2];
                        Ts[(mloc + 8) * 33 + d + 1] = acc[mf][nf][3];
                    }
                }
            }
            __syncthreads();
            #pragma unroll
            for (int dd = 0; dd < 4; dd++) {
                int d = wid * 4 + dd;
                float4 v;
                v.x = Ts[(lane * 4 + 0) * 33 + d];
                v.y = Ts[(lane * 4 + 1) * 33 + d];
                v.z = Ts[(lane * 4 + 2) * 33 + d];
                v.w = Ts[(lane * 4 + 3) * 33 + d];
                *(float4*)&Cb[(long long)(n0 + nc * 32 + d) * SS + srow0 + lane * 4] = v;
            }
        }
    }
}

// ================= RoPE (fp32, in-place on Q and K) =================
__global__ void rope_kernel(float* __restrict__ Q, float* __restrict__ Kt,
                            const int* __restrict__ pos32)
{
    long long idx = (long long)blockIdx.x * blockDim.x + threadIdx.x;
    const int half = DD / 2;
    long long total = (long long)BB * SS * half;
    if (idx >= total) return;

    int i = (int)(idx % half);
    long long row = idx / half;
    bool is64 = (pos32[1] == 0);              // int64 vs int32 positions
    int p = is64 ? pos32[2 * row] : pos32[row];

    float fexp = (float)(2 * i) / (float)DD;
    float inv_freq = exp2f(-fexp * 13.28771238f);   // log2(10000)
    float ang = (float)p * inv_freq;
    float c, sn;
    sincosf(ang, &sn, &c);

    long long off = row * DD + 2 * i;
    float q1 = Q[off], q2 = Q[off + 1];
    Q[off]     = q1 * c - q2 * sn;
    Q[off + 1] = q1 * sn + q2 * c;
    float k1 = Kt[off], k2 = Kt[off + 1];
    Kt[off]     = k1 * c - k2 * sn;
    Kt[off + 1] = k1 * sn + k2 * c;
}

// ================= causal softmax (in place, zero-fills masked tail) =================
__device__ __forceinline__ float warpMax(float v) {
    #pragma unroll
    for (int o = 16; o; o >>= 1) v = fmaxf(v, __shfl_xor_sync(0xffffffffu, v, o));
    return v;
}
__device__ __forceinline__ float warpSum(float v) {
    #pragma unroll
    for (int o = 16; o; o >>= 1) v += __shfl_xor_sync(0xffffffffu, v, o);
    return v;
}

__global__ void __launch_bounds__(256) softmax_causal(float* __restrict__ Sc)
{
    int q = blockIdx.x;
    int b = blockIdx.y;
    float* row = Sc + ((long long)b * SS + q) * SS;
    int L = q + 1;
    int tid = threadIdx.x, warp = tid >> 5, lane = tid & 31;
    __shared__ float red[8];

    float m = -1e30f;
    for (int j = tid; j < L; j += 256) m = fmaxf(m, row[j]);
    m = warpMax(m);
    if (lane == 0) red[warp] = m;
    __syncthreads();
    m = (lane < 8) ? red[lane] : -1e30f;
    m = warpMax(m);
    m = __shfl_sync(0xffffffffu, m, 0);

    float sum = 0.f;
    for (int j = tid; j < L; j += 256) {
        float e = __expf(row[j] - m);
        row[j] = e;
        sum += e;
    }
    sum = warpSum(sum);
    __syncthreads();
    if (lane == 0) red[warp] = sum;
    __syncthreads();
    sum = (lane < 8) ? red[lane] : 0.f;
    sum = warpSum(sum);
    sum = __shfl_sync(0xffffffffu, sum, 0);
    float inv = 1.f / sum;

    for (int j = tid; j < L; j += 256) row[j] *= inv;
    for (int j = L + tid; j < SS; j += 256) row[j] = 0.f;
}

// ================= launch =================
extern "C" void kernel_launch(void* const* d_in, const int* in_sizes, int n_in,
                              void* d_out, int out_size)
{
    const float* x   = (const float*)d_in[0];
    const float* Wq  = (const float*)d_in[1];
    const float* Wk  = (const float*)d_in[2];
    const float* Wv  = (const float*)d_in[3];
    const float* Wo  = (const float*)d_in[4];
    const int*   pos = (const int*)d_in[5];
    float* out = (float*)d_out;

    static float *pQ = nullptr, *pK = nullptr, *pVt = nullptr, *pS = nullptr, *pA = nullptr;
    static bool inited = false;
    if (!inited) {
        cudaGetSymbolAddress((void**)&pQ,  g_Q);
        cudaGetSymbolAddress((void**)&pK,  g_K);
        cudaGetSymbolAddress((void**)&pVt, g_Vt);
        cudaGetSymbolAddress((void**)&pS,  g_S);
        cudaGetSymbolAddress((void**)&pA,  g_A);
        cudaFuncSetAttribute(gemm_mma, cudaFuncAttributeMaxDynamicSharedMemorySize, SM_TOTAL);
        inited = true;
    }

    dim3 blk(256);
    dim3 gProj(DD / 128, MM / 128, 1);      // (8, 64)

    // Q, K projections: y = x @ W^T
    gemm_mma<<<gProj, blk, SM_TOTAL>>>(x, Wq, pQ, MM, DD, DD, 0, 0, 0, 1.f, 0);
    gemm_mma<<<gProj, blk, SM_TOTAL>>>(x, Wk, pK, MM, DD, DD, 0, 0, 0, 1.f, 0);
    // V projection, output transposed per batch -> Vt[b][d][s]
    gemm_mma<<<gProj, blk, SM_TOTAL>>>(x, Wv, pVt, MM, DD, DD, 0, 0, (long long)DD * SS, 1.f, 3);

    // RoPE on Q and K
    long long ropeThreads = (long long)BB * SS * (DD / 2);
    rope_kernel<<<(unsigned)((ropeThreads + 255) / 256), 256>>>(pQ, pK, pos);

    // scores = Q @ K^T / 32, per batch, fully-masked tiles skipped
    dim3 gS(SS / 128, SS / 128, BB);        // (16, 16, 4)
    gemm_mma<<<gS, blk, SM_TOTAL>>>(pQ, pK, pS, SS, SS, DD,
                                    (long long)SS * DD, (long long)SS * DD, (long long)SS * SS,
                                    0.03125f, 1);

    // causal softmax (zero-fills above diagonal)
    softmax_causal<<<dim3(SS, BB), 256>>>(pS);

    // attn = P @ Vt^T, per batch, K-loop truncated at diagonal
    dim3 gPV(DD / 128, SS / 128, BB);       // (8, 16, 4)
    gemm_mma<<<gPV, blk, SM_TOTAL>>>(pS, pVt, pA, SS, DD, SS,
                                     (long long)SS * SS, (long long)DD * SS, (long long)SS * DD,
                                     1.f, 2);

    // out = attn @ Wo^T
    gemm_mma<<<gProj, blk, SM_TOTAL>>>(pA, Wo, out, MM, DD, DD, 0, 0, 0, 1.f, 0);
}